// round 11
// baseline (speedup 1.0000x reference)
#include <cuda_runtime.h>
#include <cuda_fp16.h>
#include <math.h>
#include <stdint.h>

#define BB 64
#define TT 1024
#define NDIM 1024
#define MTOT (BB*TT)

__device__ __align__(16) __half g_h16[(size_t)MTOT*NDIM];
__device__ __align__(16) __half g_w[(size_t)NDIM*NDIM];
__device__ float g_dec_fea[BB*NDIM];
__device__ float g_scores[MTOT];
__device__ float g_ct_part[4*BB*NDIM];

// ---------------- helpers ----------------
__device__ __forceinline__ uint32_t smem_to_u32(const void* p) {
    uint32_t a;
    asm("{ .reg .u64 t; cvta.to.shared.u64 t, %1; cvt.u32.u64 %0, t; }" : "=r"(a) : "l"(p));
    return a;
}
__device__ __forceinline__ void cp16(uint32_t dst, const void* src) {
    asm volatile("cp.async.cg.shared.global [%0], [%1], 16;" :: "r"(dst), "l"(src));
}
#define CP_COMMIT() asm volatile("cp.async.commit_group;" ::: "memory")
#define CP_WAIT_2() asm volatile("cp.async.wait_group 2;" ::: "memory")
#define CP_WAIT_0() asm volatile("cp.async.wait_group 0;" ::: "memory")

__device__ __forceinline__ void ldm_x4(uint32_t* r, uint32_t addr) {
    asm volatile("ldmatrix.sync.aligned.m8n8.x4.shared.b16 {%0,%1,%2,%3}, [%4];"
        : "=r"(r[0]), "=r"(r[1]), "=r"(r[2]), "=r"(r[3]) : "r"(addr));
}
__device__ __forceinline__ void mma16816(float* d, const uint32_t* a, const uint32_t* b) {
    asm volatile("mma.sync.aligned.m16n8k16.row.col.f32.f16.f16.f32 "
        "{%0,%1,%2,%3}, {%4,%5,%6,%7}, {%8,%9}, {%0,%1,%2,%3};"
        : "+f"(d[0]), "+f"(d[1]), "+f"(d[2]), "+f"(d[3])
        : "r"(a[0]), "r"(a[1]), "r"(a[2]), "r"(a[3]), "r"(b[0]), "r"(b[1]));
}

// ---------------- convert f32 -> fp16 ----------------
__global__ void conv_h_kernel(const float* __restrict__ src) {
    const size_t i = (size_t)blockIdx.x * 256 + threadIdx.x;
    float4 x = ((const float4*)src)[i];
    __half2* H = (__half2*)g_h16;
    H[2*i]   = __halves2half2(__float2half_rn(x.x), __float2half_rn(x.y));
    H[2*i+1] = __halves2half2(__float2half_rn(x.z), __float2half_rn(x.w));
}
__global__ void conv_w_kernel(const float* __restrict__ src) {
    const size_t i = (size_t)blockIdx.x * 256 + threadIdx.x;
    float4 x = ((const float4*)src)[i];
    __half2* W = (__half2*)g_w;
    W[2*i]   = __halves2half2(__float2half_rn(x.x), __float2half_rn(x.y));
    W[2*i+1] = __halves2half2(__float2half_rn(x.z), __float2half_rn(x.w));
}

// ---------------- dec_fea ----------------
__global__ void dec_fea_kernel(const float* __restrict__ s_t_hat,
                               const float* __restrict__ dec_W,
                               const float* __restrict__ dec_b) {
    const int warp = threadIdx.x >> 5, lane = threadIdx.x & 31;
    const int m = blockIdx.x * 8 + warp;
    const float* wr = dec_W + (size_t)m * NDIM + lane;
    float w[32];
#pragma unroll
    for (int j = 0; j < 32; ++j) w[j] = wr[j * 32];
    const float bias = dec_b[m];
    for (int b = 0; b < BB; ++b) {
        const float* s = s_t_hat + (size_t)b * NDIM + lane;
        float acc = 0.f;
#pragma unroll
        for (int j = 0; j < 32; ++j) acc += w[j] * s[j * 32];
#pragma unroll
        for (int off = 16; off; off >>= 1) acc += __shfl_down_sync(0xffffffffu, acc, off);
        if (lane == 0) g_dec_fea[b * NDIM + m] = acc + bias;
    }
}

// ---------------- score kernel: 64x128 CTA tile, 128 thr, 3 CTAs/SM ----------------
#define PITCH  80
#define BUFA   (64*PITCH)                  /* 5120 */
#define BUFB   (128*PITCH)                 /* 10240 */
#define OFF_B  BUFA
#define STGB   (BUFA+BUFB)                 /* 15360 */
#define NSTG   4
#define OFF_DEC (NSTG*STGB)                /* 61440: 128 floats */
#define OFF_WC  (OFF_DEC+512)
#define OFF_V   (OFF_WC+512)
#define OFF_COV (OFF_V+512)                /* 64 floats */
#define OFF_RED (OFF_COV+256)              /* 64*4 floats */
#define OFF_SC  (OFF_RED+1024)
#define SMEM_SZ (OFF_SC+256)               /* 64512 B */

__device__ __forceinline__ void load_stage(uint32_t sb, int s,
                                           int row0, int m0, int k0, int tid) {
    const uint32_t base = sb + s * STGB;
#pragma unroll
    for (int it = 0; it < 2; ++it) {   // A: 64 rows x 4 chunks
        const int idx = tid + it * 128;
        const int row = idx >> 2, ch = idx & 3;
        const uint32_t o = row * PITCH + ch * 16;
        const size_t g = (size_t)(row0 + row) * NDIM + k0 + ch * 8;
        cp16(base + o, g_h16 + g);
    }
#pragma unroll
    for (int it = 0; it < 4; ++it) {   // B: 128 rows x 4 chunks
        const int idx = tid + it * 128;
        const int row = idx >> 2, ch = idx & 3;
        const uint32_t o = row * PITCH + ch * 16;
        const size_t g = (size_t)(m0 + row) * NDIM + k0 + ch * 8;
        cp16(base + OFF_B + o, g_w + g);
    }
}

__global__ __launch_bounds__(128, 3)
void score_mma_kernel(const float* __restrict__ coverage,
                      const float* __restrict__ W_c,
                      const float* __restrict__ v) {
    extern __shared__ char smem[];
    const uint32_t sb = smem_to_u32(smem);
    const int tid  = threadIdx.x;
    const int lane = tid & 31;
    const int wn   = tid >> 5;          // warp = 32-col slab, all 64 rows
    const int row0 = blockIdx.x * 64;
    const int b    = row0 / TT;

    float* dec_s = (float*)(smem + OFF_DEC);
    float* wc_s  = (float*)(smem + OFF_WC);
    float* v_s   = (float*)(smem + OFF_V);
    float* cov_s = (float*)(smem + OFF_COV);
    float* red   = (float*)(smem + OFF_RED);   // [64][4]
    float* sc_s  = (float*)(smem + OFF_SC);

    if (tid < 64) {
        cov_s[tid] = coverage[row0 + tid];
        sc_s[tid]  = 0.f;
    }

    const uint32_t aoff = (uint32_t)(((lane&7) + ((lane>>3)&1)*8) * PITCH + (lane>>4)*16);
    const uint32_t boff = (uint32_t)((wn*32 + (lane&7)) * PITCH + (lane>>3)*16);

    for (int nc = 0; nc < 8; ++nc) {
        const int m0 = nc * 128;
        dec_s[tid] = g_dec_fea[b * NDIM + m0 + tid];
        wc_s[tid]  = W_c[m0 + tid];
        v_s[tid]   = v[m0 + tid];

        float acc[4][4][4];
#pragma unroll
        for (int mi = 0; mi < 4; ++mi)
#pragma unroll
            for (int ni = 0; ni < 4; ++ni)
#pragma unroll
                for (int q = 0; q < 4; ++q) acc[mi][ni][q] = 0.f;

        load_stage(sb, 0, row0, m0, 0,  tid); CP_COMMIT();
        load_stage(sb, 1, row0, m0, 32, tid); CP_COMMIT();
        load_stage(sb, 2, row0, m0, 64, tid); CP_COMMIT();

        for (int ks = 0; ks < 32; ++ks) {
            const int s = ks & 3;
            if (ks + 3 < 32) CP_WAIT_2(); else CP_WAIT_0();
            __syncthreads();
            if (ks + 3 < 32) {
                load_stage(sb, (ks + 3) & 3, row0, m0, (ks + 3) * 32, tid);
                CP_COMMIT();
            }
            const uint32_t stg = sb + s * STGB;

            uint32_t bh[4][4];
#pragma unroll
            for (int ni = 0; ni < 4; ++ni)
                ldm_x4(bh[ni], stg + OFF_B + boff + ni * (8 * PITCH));
#pragma unroll
            for (int kk = 0; kk < 2; ++kk) {
                uint32_t ah[4][4];
#pragma unroll
                for (int mi = 0; mi < 4; ++mi)
                    ldm_x4(ah[mi], stg + aoff + mi * (16 * PITCH) + kk * 32);
#pragma unroll
                for (int mi = 0; mi < 4; ++mi)
#pragma unroll
                    for (int ni = 0; ni < 4; ++ni)
                        mma16816(acc[mi][ni], ah[mi], &bh[ni][kk*2]);
            }
        }

        // fused epilogue: tanh + dot with v over this 128-col chunk
        float part[4][2];
#pragma unroll
        for (int mi = 0; mi < 4; ++mi) { part[mi][0] = 0.f; part[mi][1] = 0.f; }
#pragma unroll
        for (int mi = 0; mi < 4; ++mi) {
            const int r0 = mi*16 + (lane >> 2);
            const float cv0 = cov_s[r0], cv1 = cov_s[r0 + 8];
#pragma unroll
            for (int ni = 0; ni < 4; ++ni) {
                const int c0 = wn*32 + ni*8 + (lane & 3)*2;
                const float d0 = dec_s[c0],  d1 = dec_s[c0+1];
                const float w0 = wc_s[c0],   w1 = wc_s[c0+1];
                const float q0 = v_s[c0],    q1 = v_s[c0+1];
                part[mi][0] += tanhf(acc[mi][ni][0] + d0 + cv0*w0) * q0
                             + tanhf(acc[mi][ni][1] + d1 + cv0*w1) * q1;
                part[mi][1] += tanhf(acc[mi][ni][2] + d0 + cv1*w0) * q0
                             + tanhf(acc[mi][ni][3] + d1 + cv1*w1) * q1;
            }
        }
#pragma unroll
        for (int mi = 0; mi < 4; ++mi)
#pragma unroll
            for (int i = 0; i < 2; ++i) {
                float p = part[mi][i];
                p += __shfl_xor_sync(0xffffffffu, p, 1);
                p += __shfl_xor_sync(0xffffffffu, p, 2);
                if ((lane & 3) == 0)
                    red[(mi*16 + (lane >> 2) + 8*i) * 4 + wn] = p;
            }
        __syncthreads();
        if (tid < 64)
            sc_s[tid] += red[tid*4] + red[tid*4+1] + red[tid*4+2] + red[tid*4+3];
        __syncthreads();
    }

    if (tid < 64) g_scores[row0 + tid] = sc_s[tid];
}

// ---------------- softmax ----------------
__global__ void softmax_kernel(const float* __restrict__ mask,
                               const float* __restrict__ coverage,
                               float* __restrict__ attn_out,
                               float* __restrict__ cov_out) {
    const int b = blockIdx.x, tid = threadIdx.x;
    __shared__ float wr_[8], stat[2];
    const float* sc = g_scores + b * TT;
    float sv[4], lmax = -1e30f;
#pragma unroll
    for (int q = 0; q < 4; ++q) { sv[q] = sc[tid + 256 * q]; lmax = fmaxf(lmax, sv[q]); }
#pragma unroll
    for (int off = 16; off; off >>= 1) lmax = fmaxf(lmax, __shfl_xor_sync(0xffffffffu, lmax, off));
    if ((tid & 31) == 0) wr_[tid >> 5] = lmax;
    __syncthreads();
    if (tid == 0) {
        float m = wr_[0];
#pragma unroll
        for (int i = 1; i < 8; ++i) m = fmaxf(m, wr_[i]);
        stat[0] = m;
    }
    __syncthreads();
    const float M = stat[0];
    float e[4], lsum = 0.f;
#pragma unroll
    for (int q = 0; q < 4; ++q) { e[q] = expf(sv[q] - M) * mask[b * TT + tid + 256 * q]; lsum += e[q]; }
#pragma unroll
    for (int off = 16; off; off >>= 1) lsum += __shfl_xor_sync(0xffffffffu, lsum, off);
    if ((tid & 31) == 0) wr_[tid >> 5] = lsum;
    __syncthreads();
    if (tid == 0) {
        float s = 0.f;
#pragma unroll
        for (int i = 0; i < 8; ++i) s += wr_[i];
        stat[1] = 1.0f / s;
    }
    __syncthreads();
    const float inv = stat[1];
#pragma unroll
    for (int q = 0; q < 4; ++q) {
        const int t = tid + 256 * q;
        const float a = e[q] * inv;
        attn_out[b * TT + t] = a;
        cov_out[b * TT + t]  = coverage[b * TT + t] + a;
    }
}

// ---------------- c_t: 4-way T-split on fp16 h + reduce ----------------
__global__ void ct_part_kernel(const float* __restrict__ attn) {
    const int b = blockIdx.x, nb = blockIdx.y, tc = blockIdx.z;
    const int n2 = nb * 128 + threadIdx.x;           // half2 column index
    __shared__ float a_s[256];
    for (int i = threadIdx.x; i < 256; i += 128)
        a_s[i] = attn[b * TT + tc * 256 + i];
    __syncthreads();
    const __half2* hb = (const __half2*)g_h16 + (size_t)(b * TT + tc * 256) * (NDIM/2) + n2;
    float s0 = 0.f, s1 = 0.f;
#pragma unroll 4
    for (int t = 0; t < 256; ++t) {
        const float2 hv = __half22float2(hb[(size_t)t * (NDIM/2)]);
        const float a = a_s[t];
        s0 += a * hv.x;
        s1 += a * hv.y;
    }
    float2* outp = (float2*)(g_ct_part + ((size_t)tc * BB + b) * NDIM) + n2;
    *outp = make_float2(s0, s1);
}
__global__ void ct_reduce_kernel(float* __restrict__ c_t) {
    const int i = blockIdx.x * 256 + threadIdx.x;
    c_t[i] = (g_ct_part[i] + g_ct_part[i + BB * NDIM]) +
             (g_ct_part[i + 2 * BB * NDIM] + g_ct_part[i + 3 * BB * NDIM]);
}

// ---------------------------------------------------------------------------
extern "C" void kernel_launch(void* const* d_in, const int* in_sizes, int n_in,
                              void* d_out, int out_size) {
    const float* s_t_hat  = (const float*)d_in[0];
    const float* h        = (const float*)d_in[1];
    const float* mask     = (const float*)d_in[2];
    const float* coverage = (const float*)d_in[3];
    const float* W_h      = (const float*)d_in[4];
    const float* W_c      = (const float*)d_in[5];
    const float* dec_W    = (const float*)d_in[6];
    const float* dec_b    = (const float*)d_in[7];
    const float* v        = (const float*)d_in[8];

    float* out  = (float*)d_out;
    float* c_t  = out;
    float* attn = out + (size_t)BB * NDIM;
    float* covn = attn + (size_t)BB * TT;

    cudaFuncSetAttribute(score_mma_kernel,
                         cudaFuncAttributeMaxDynamicSharedMemorySize, SMEM_SZ);

    conv_h_kernel<<<(int)((size_t)MTOT * NDIM / 4 / 256), 256>>>(h);
    conv_w_kernel<<<NDIM * NDIM / 4 / 256, 256>>>(W_h);
    dec_fea_kernel<<<NDIM / 8, 256>>>(s_t_hat, dec_W, dec_b);
    score_mma_kernel<<<MTOT / 64, 128, SMEM_SZ>>>(coverage, W_c, v);
    softmax_kernel<<<BB, 256>>>(mask, coverage, attn, covn);
    ct_part_kernel<<<dim3(BB, 4, 4), 128>>>(attn);
    ct_reduce_kernel<<<BB * NDIM / 256, 256>>>(c_t);
}

// round 13
// speedup vs baseline: 1.0259x; 1.0259x over previous
#include <cuda_runtime.h>
#include <cuda_fp16.h>
#include <math.h>
#include <stdint.h>

#define BB 64
#define TT 1024
#define NDIM 1024
#define MTOT (BB*TT)

__device__ __align__(16) __half g_h16[(size_t)MTOT*NDIM];
__device__ __align__(16) __half g_w[(size_t)NDIM*NDIM];
__device__ float g_dec_fea[BB*NDIM];
__device__ float g_scores[MTOT];
__device__ float g_ct_part[4*BB*NDIM];

#define H_BLOCKS ((int)((size_t)MTOT * NDIM / 4 / 256))   /* 65536 */
#define W_BLOCKS (NDIM * NDIM / 4 / 256)                  /* 1024 */

// ---------------- helpers ----------------
__device__ __forceinline__ uint32_t smem_to_u32(const void* p) {
    uint32_t a;
    asm("{ .reg .u64 t; cvta.to.shared.u64 t, %1; cvt.u32.u64 %0, t; }" : "=r"(a) : "l"(p));
    return a;
}
__device__ __forceinline__ void cp16(uint32_t dst, const void* src) {
    asm volatile("cp.async.cg.shared.global [%0], [%1], 16;" :: "r"(dst), "l"(src));
}
#define CP_COMMIT() asm volatile("cp.async.commit_group;" ::: "memory")
#define CP_WAIT_2() asm volatile("cp.async.wait_group 2;" ::: "memory")
#define CP_WAIT_0() asm volatile("cp.async.wait_group 0;" ::: "memory")

__device__ __forceinline__ void ldm_x4(uint32_t* r, uint32_t addr) {
    asm volatile("ldmatrix.sync.aligned.m8n8.x4.shared.b16 {%0,%1,%2,%3}, [%4];"
        : "=r"(r[0]), "=r"(r[1]), "=r"(r[2]), "=r"(r[3]) : "r"(addr));
}
__device__ __forceinline__ void mma16816(float* d, const uint32_t* a, const uint32_t* b) {
    asm volatile("mma.sync.aligned.m16n8k16.row.col.f32.f16.f16.f32 "
        "{%0,%1,%2,%3}, {%4,%5,%6,%7}, {%8,%9}, {%0,%1,%2,%3};"
        : "+f"(d[0]), "+f"(d[1]), "+f"(d[2]), "+f"(d[3])
        : "r"(a[0]), "r"(a[1]), "r"(a[2]), "r"(a[3]), "r"(b[0]), "r"(b[1]));
}

// ---------------- convert f32 -> fp16 (h and W in one kernel) ----------------
__global__ void conv_kernel(const float* __restrict__ h, const float* __restrict__ w) {
    const int blk = blockIdx.x;
    if (blk < H_BLOCKS) {
        const size_t i = (size_t)blk * 256 + threadIdx.x;
        float4 x = ((const float4*)h)[i];
        __half2* H = (__half2*)g_h16;
        H[2*i]   = __halves2half2(__float2half_rn(x.x), __float2half_rn(x.y));
        H[2*i+1] = __halves2half2(__float2half_rn(x.z), __float2half_rn(x.w));
    } else {
        const size_t i = (size_t)(blk - H_BLOCKS) * 256 + threadIdx.x;
        float4 x = ((const float4*)w)[i];
        __half2* W = (__half2*)g_w;
        W[2*i]   = __halves2half2(__float2half_rn(x.x), __float2half_rn(x.y));
        W[2*i+1] = __halves2half2(__float2half_rn(x.z), __float2half_rn(x.w));
    }
}

// ---------------- dec_fea ----------------
__global__ void dec_fea_kernel(const float* __restrict__ s_t_hat,
                               const float* __restrict__ dec_W,
                               const float* __restrict__ dec_b) {
    const int warp = threadIdx.x >> 5, lane = threadIdx.x & 31;
    const int m = blockIdx.x * 8 + warp;
    const float* wr = dec_W + (size_t)m * NDIM + lane;
    float w[32];
#pragma unroll
    for (int j = 0; j < 32; ++j) w[j] = wr[j * 32];
    const float bias = dec_b[m];
    for (int b = 0; b < BB; ++b) {
        const float* s = s_t_hat + (size_t)b * NDIM + lane;
        float acc = 0.f;
#pragma unroll
        for (int j = 0; j < 32; ++j) acc += w[j] * s[j * 32];
#pragma unroll
        for (int off = 16; off; off >>= 1) acc += __shfl_down_sync(0xffffffffu, acc, off);
        if (lane == 0) g_dec_fea[b * NDIM + m] = acc + bias;
    }
}

// ---------------- score kernel: 64x256 CTA tile, 128 thr, 2 CTAs/SM ----------------
// R10-proven schedule: wait -> sync -> (LDSM first, then cp.async burst) -> MMAs.
#define PITCH  80
#define BUFA   (64*PITCH)                  /* 5120 */
#define BUFB   (256*PITCH)                 /* 20480 */
#define OFF_B  BUFA
#define STGB   (BUFA+BUFB)                 /* 25600 */
#define NSTG   4
#define OFF_DEC (NSTG*STGB)                /* 102400: 256 floats */
#define OFF_WC  (OFF_DEC+1024)
#define OFF_V   (OFF_WC+1024)
#define OFF_COV (OFF_V+1024)               /* 64 floats */
#define OFF_RED (OFF_COV+256)              /* 64*4 floats */
#define OFF_SC  (OFF_RED+1024)
#define SMEM_SZ (OFF_SC+256)               /* 107008 B */

__device__ __forceinline__ void load_stage(uint32_t sb, int s,
                                           int row0, int m0, int k0, int tid) {
    const uint32_t base = sb + s * STGB;
#pragma unroll
    for (int it = 0; it < 2; ++it) {   // A: 64 rows x 4 chunks
        const int idx = tid + it * 128;
        const int row = idx >> 2, ch = idx & 3;
        const uint32_t o = row * PITCH + ch * 16;
        const size_t g = (size_t)(row0 + row) * NDIM + k0 + ch * 8;
        cp16(base + o, g_h16 + g);
    }
#pragma unroll
    for (int it = 0; it < 8; ++it) {   // B: 256 rows x 4 chunks
        const int idx = tid + it * 128;
        const int row = idx >> 2, ch = idx & 3;
        const uint32_t o = row * PITCH + ch * 16;
        const size_t g = (size_t)(m0 + row) * NDIM + k0 + ch * 8;
        cp16(base + OFF_B + o, g_w + g);
    }
}

__global__ __launch_bounds__(128, 2)
void score_mma_kernel(const float* __restrict__ coverage,
                      const float* __restrict__ W_c,
                      const float* __restrict__ v) {
    extern __shared__ char smem[];
    const uint32_t sb = smem_to_u32(smem);
    const int tid  = threadIdx.x;
    const int lane = tid & 31;
    const int wn   = tid >> 5;          // warp = 64-col slab, all 64 rows
    const int row0 = blockIdx.x * 64;
    const int b    = row0 / TT;

    float* dec_s = (float*)(smem + OFF_DEC);
    float* wc_s  = (float*)(smem + OFF_WC);
    float* v_s   = (float*)(smem + OFF_V);
    float* cov_s = (float*)(smem + OFF_COV);
    float* red   = (float*)(smem + OFF_RED);   // [64][4]
    float* sc_s  = (float*)(smem + OFF_SC);

    if (tid < 64) {
        cov_s[tid] = coverage[row0 + tid];
        sc_s[tid]  = 0.f;
    }

    const uint32_t aoff = (uint32_t)(((lane&7) + ((lane>>3)&1)*8) * PITCH + (lane>>4)*16);
    const uint32_t boff = (uint32_t)((wn*64 + (lane&7)) * PITCH + (lane>>3)*16);

    for (int nc = 0; nc < 4; ++nc) {
        const int m0 = nc * 256;
        dec_s[tid]       = g_dec_fea[b * NDIM + m0 + tid];
        dec_s[tid + 128] = g_dec_fea[b * NDIM + m0 + tid + 128];
        wc_s[tid]        = W_c[m0 + tid];
        wc_s[tid + 128]  = W_c[m0 + tid + 128];
        v_s[tid]         = v[m0 + tid];
        v_s[tid + 128]   = v[m0 + tid + 128];

        float acc[4][8][4];
#pragma unroll
        for (int mi = 0; mi < 4; ++mi)
#pragma unroll
            for (int ni = 0; ni < 8; ++ni)
#pragma unroll
                for (int q = 0; q < 4; ++q) acc[mi][ni][q] = 0.f;

        load_stage(sb, 0, row0, m0, 0,  tid); CP_COMMIT();
        load_stage(sb, 1, row0, m0, 32, tid); CP_COMMIT();
        load_stage(sb, 2, row0, m0, 64, tid); CP_COMMIT();

        for (int ks = 0; ks < 32; ++ks) {
            const int s = ks & 3;
            if (ks + 3 < 32) CP_WAIT_2(); else CP_WAIT_0();
            __syncthreads();
            const uint32_t stg = sb + s * STGB;

            // Start LDSM latency clocks first: all B frags + kk0 A frags.
            uint32_t bh[8][4];
#pragma unroll
            for (int ni = 0; ni < 8; ++ni)
                ldm_x4(bh[ni], stg + OFF_B + boff + ni * (8 * PITCH));
            uint32_t a0[4][4];
#pragma unroll
            for (int mi = 0; mi < 4; ++mi)
                ldm_x4(a0[mi], stg + aoff + mi * (16 * PITCH));

            // Overlap LDSM latency with next-stage cp.async issue burst.
            if (ks + 3 < 32) {
                load_stage(sb, (ks + 3) & 3, row0, m0, (ks + 3) * 32, tid);
                CP_COMMIT();
            }

            // kk = 0
#pragma unroll
            for (int mi = 0; mi < 4; ++mi)
#pragma unroll
                for (int ni = 0; ni < 8; ++ni)
                    mma16816(acc[mi][ni], a0[mi], &bh[ni][0]);
            // kk = 1
            uint32_t a1[4][4];
#pragma unroll
            for (int mi = 0; mi < 4; ++mi)
                ldm_x4(a1[mi], stg + aoff + mi * (16 * PITCH) + 32);
#pragma unroll
            for (int mi = 0; mi < 4; ++mi)
#pragma unroll
                for (int ni = 0; ni < 8; ++ni)
                    mma16816(acc[mi][ni], a1[mi], &bh[ni][2]);
        }

        // fused epilogue: tanh + dot with v over this 256-col chunk
        float part[4][2];
#pragma unroll
        for (int mi = 0; mi < 4; ++mi) { part[mi][0] = 0.f; part[mi][1] = 0.f; }
#pragma unroll
        for (int mi = 0; mi < 4; ++mi) {
            const int r0 = mi*16 + (lane >> 2);
            const float cv0 = cov_s[r0], cv1 = cov_s[r0 + 8];
#pragma unroll
            for (int ni = 0; ni < 8; ++ni) {
                const int c0 = wn*64 + ni*8 + (lane & 3)*2;
                const float d0 = dec_s[c0],  d1 = dec_s[c0+1];
                const float w0 = wc_s[c0],   w1 = wc_s[c0+1];
                const float q0 = v_s[c0],    q1 = v_s[c0+1];
                part[mi][0] += tanhf(acc[mi][ni][0] + d0 + cv0*w0) * q0
                             + tanhf(acc[mi][ni][1] + d1 + cv0*w1) * q1;
                part[mi][1] += tanhf(acc[mi][ni][2] + d0 + cv1*w0) * q0
                             + tanhf(acc[mi][ni][3] + d1 + cv1*w1) * q1;
            }
        }
#pragma unroll
        for (int mi = 0; mi < 4; ++mi)
#pragma unroll
            for (int i = 0; i < 2; ++i) {
                float p = part[mi][i];
                p += __shfl_xor_sync(0xffffffffu, p, 1);
                p += __shfl_xor_sync(0xffffffffu, p, 2);
                if ((lane & 3) == 0)
                    red[(mi*16 + (lane >> 2) + 8*i) * 4 + wn] = p;
            }
        __syncthreads();
        if (tid < 64)
            sc_s[tid] += red[tid*4] + red[tid*4+1] + red[tid*4+2] + red[tid*4+3];
        __syncthreads();
    }

    if (tid < 64) g_scores[row0 + tid] = sc_s[tid];
}

// ---------------- softmax ----------------
__global__ void softmax_kernel(const float* __restrict__ mask,
                               const float* __restrict__ coverage,
                               float* __restrict__ attn_out,
                               float* __restrict__ cov_out) {
    const int b = blockIdx.x, tid = threadIdx.x;
    __shared__ float wr_[8], stat[2];
    const float* sc = g_scores + b * TT;
    float sv[4], lmax = -1e30f;
#pragma unroll
    for (int q = 0; q < 4; ++q) { sv[q] = sc[tid + 256 * q]; lmax = fmaxf(lmax, sv[q]); }
#pragma unroll
    for (int off = 16; off; off >>= 1) lmax = fmaxf(lmax, __shfl_xor_sync(0xffffffffu, lmax, off));
    if ((tid & 31) == 0) wr_[tid >> 5] = lmax;
    __syncthreads();
    if (tid == 0) {
        float m = wr_[0];
#pragma unroll
        for (int i = 1; i < 8; ++i) m = fmaxf(m, wr_[i]);
        stat[0] = m;
    }
    __syncthreads();
    const float M = stat[0];
    float e[4], lsum = 0.f;
#pragma unroll
    for (int q = 0; q < 4; ++q) { e[q] = expf(sv[q] - M) * mask[b * TT + tid + 256 * q]; lsum += e[q]; }
#pragma unroll
    for (int off = 16; off; off >>= 1) lsum += __shfl_xor_sync(0xffffffffu, lsum, off);
    if ((tid & 31) == 0) wr_[tid >> 5] = lsum;
    __syncthreads();
    if (tid == 0) {
        float s = 0.f;
#pragma unroll
        for (int i = 0; i < 8; ++i) s += wr_[i];
        stat[1] = 1.0f / s;
    }
    __syncthreads();
    const float inv = stat[1];
#pragma unroll
    for (int q = 0; q < 4; ++q) {
        const int t = tid + 256 * q;
        const float a = e[q] * inv;
        attn_out[b * TT + t] = a;
        cov_out[b * TT + t]  = coverage[b * TT + t] + a;
    }
}

// ---------------- c_t: 4-way T-split on fp16 h + reduce ----------------
__global__ void ct_part_kernel(const float* __restrict__ attn) {
    const int b = blockIdx.x, nb = blockIdx.y, tc = blockIdx.z;
    const int n2 = nb * 128 + threadIdx.x;           // half2 column index
    __shared__ float a_s[256];
    for (int i = threadIdx.x; i < 256; i += 128)
        a_s[i] = attn[b * TT + tc * 256 + i];
    __syncthreads();
    const __half2* hb = (const __half2*)g_h16 + (size_t)(b * TT + tc * 256) * (NDIM/2) + n2;
    float s0 = 0.f, s1 = 0.f;
#pragma unroll 4
    for (int t = 0; t < 256; ++t) {
        const float2 hv = __half22float2(hb[(size_t)t * (NDIM/2)]);
        const float a = a_s[t];
        s0 += a * hv.x;
        s1 += a * hv.y;
    }
    float2* outp = (float2*)(g_ct_part + ((size_t)tc * BB + b) * NDIM) + n2;
    *outp = make_float2(s0, s1);
}
__global__ void ct_reduce_kernel(float* __restrict__ c_t) {
    const int i = blockIdx.x * 256 + threadIdx.x;
    c_t[i] = (g_ct_part[i] + g_ct_part[i + BB * NDIM]) +
             (g_ct_part[i + 2 * BB * NDIM] + g_ct_part[i + 3 * BB * NDIM]);
}

// ---------------------------------------------------------------------------
extern "C" void kernel_launch(void* const* d_in, const int* in_sizes, int n_in,
                              void* d_out, int out_size) {
    const float* s_t_hat  = (const float*)d_in[0];
    const float* h        = (const float*)d_in[1];
    const float* mask     = (const float*)d_in[2];
    const float* coverage = (const float*)d_in[3];
    const float* W_h      = (const float*)d_in[4];
    const float* W_c      = (const float*)d_in[5];
    const float* dec_W    = (const float*)d_in[6];
    const float* dec_b    = (const float*)d_in[7];
    const float* v        = (const float*)d_in[8];

    float* out  = (float*)d_out;
    float* c_t  = out;
    float* attn = out + (size_t)BB * NDIM;
    float* covn = attn + (size_t)BB * TT;

    cudaFuncSetAttribute(score_mma_kernel,
                         cudaFuncAttributeMaxDynamicSharedMemorySize, SMEM_SZ);

    conv_kernel<<<H_BLOCKS + W_BLOCKS, 256>>>(h, W_h);
    dec_fea_kernel<<<NDIM / 8, 256>>>(s_t_hat, dec_W, dec_b);
    score_mma_kernel<<<MTOT / 64, 128, SMEM_SZ>>>(coverage, W_c, v);
    softmax_kernel<<<BB, 256>>>(mask, coverage, attn, covn);
    ct_part_kernel<<<dim3(BB, 4, 4), 128>>>(attn);
    ct_reduce_kernel<<<BB * NDIM / 256, 256>>>(c_t);
}

// round 14
// speedup vs baseline: 1.0621x; 1.0353x over previous
#include <cuda_runtime.h>
#include <cuda_fp16.h>
#include <math.h>
#include <stdint.h>

#define BB 64
#define TT 1024
#define NDIM 1024
#define MTOT (BB*TT)

__device__ __align__(16) __half g_h16[(size_t)MTOT*NDIM];
__device__ __align__(16) __half g_w[(size_t)NDIM*NDIM];
__device__ float g_dec_fea[BB*NDIM];
__device__ float g_scores[MTOT];
__device__ float g_ct_part[4*BB*NDIM];

#define H_BLOCKS ((int)((size_t)MTOT * NDIM / 4 / 256))   /* 65536 */
#define W_BLOCKS (NDIM * NDIM / 4 / 256)                  /* 1024 */

// ---------------- helpers ----------------
__device__ __forceinline__ uint32_t smem_to_u32(const void* p) {
    uint32_t a;
    asm("{ .reg .u64 t; cvta.to.shared.u64 t, %1; cvt.u32.u64 %0, t; }" : "=r"(a) : "l"(p));
    return a;
}
__device__ __forceinline__ void cp16(uint32_t dst, const void* src) {
    asm volatile("cp.async.cg.shared.global [%0], [%1], 16;" :: "r"(dst), "l"(src));
}
#define CP_COMMIT() asm volatile("cp.async.commit_group;" ::: "memory")
#define CP_WAIT_2() asm volatile("cp.async.wait_group 2;" ::: "memory")
#define CP_WAIT_0() asm volatile("cp.async.wait_group 0;" ::: "memory")

__device__ __forceinline__ void ldm_x4(uint32_t* r, uint32_t addr) {
    asm volatile("ldmatrix.sync.aligned.m8n8.x4.shared.b16 {%0,%1,%2,%3}, [%4];"
        : "=r"(r[0]), "=r"(r[1]), "=r"(r[2]), "=r"(r[3]) : "r"(addr));
}
__device__ __forceinline__ void mma16816(float* d, const uint32_t* a, const uint32_t* b) {
    asm volatile("mma.sync.aligned.m16n8k16.row.col.f32.f16.f16.f32 "
        "{%0,%1,%2,%3}, {%4,%5,%6,%7}, {%8,%9}, {%0,%1,%2,%3};"
        : "+f"(d[0]), "+f"(d[1]), "+f"(d[2]), "+f"(d[3])
        : "r"(a[0]), "r"(a[1]), "r"(a[2]), "r"(a[3]), "r"(b[0]), "r"(b[1]));
}
// fast tanh: 1 - 2/(e^{2x}+1); exact saturation at +-1; err ~1e-6
__device__ __forceinline__ float fast_tanh(float x) {
    const float e = __expf(2.0f * x);
    return 1.0f - __fdividef(2.0f, e + 1.0f);
}

// ---------------- convert f32 -> fp16 (h and W in one kernel) ----------------
__global__ void conv_kernel(const float* __restrict__ h, const float* __restrict__ w) {
    const int blk = blockIdx.x;
    if (blk < H_BLOCKS) {
        const size_t i = (size_t)blk * 256 + threadIdx.x;
        float4 x = ((const float4*)h)[i];
        __half2* H = (__half2*)g_h16;
        H[2*i]   = __halves2half2(__float2half_rn(x.x), __float2half_rn(x.y));
        H[2*i+1] = __halves2half2(__float2half_rn(x.z), __float2half_rn(x.w));
    } else {
        const size_t i = (size_t)(blk - H_BLOCKS) * 256 + threadIdx.x;
        float4 x = ((const float4*)w)[i];
        __half2* W = (__half2*)g_w;
        W[2*i]   = __halves2half2(__float2half_rn(x.x), __float2half_rn(x.y));
        W[2*i+1] = __halves2half2(__float2half_rn(x.z), __float2half_rn(x.w));
    }
}

// ---------------- dec_fea ----------------
__global__ void dec_fea_kernel(const float* __restrict__ s_t_hat,
                               const float* __restrict__ dec_W,
                               const float* __restrict__ dec_b) {
    const int warp = threadIdx.x >> 5, lane = threadIdx.x & 31;
    const int m = blockIdx.x * 8 + warp;
    const float* wr = dec_W + (size_t)m * NDIM + lane;
    float w[32];
#pragma unroll
    for (int j = 0; j < 32; ++j) w[j] = wr[j * 32];
    const float bias = dec_b[m];
    for (int b = 0; b < BB; ++b) {
        const float* s = s_t_hat + (size_t)b * NDIM + lane;
        float acc = 0.f;
#pragma unroll
        for (int j = 0; j < 32; ++j) acc += w[j] * s[j * 32];
#pragma unroll
        for (int off = 16; off; off >>= 1) acc += __shfl_down_sync(0xffffffffu, acc, off);
        if (lane == 0) g_dec_fea[b * NDIM + m] = acc + bias;
    }
}

// ---------------- score kernel: 128x128 CTA tile, 128 thr, 2 CTAs/SM ----------------
// Warp grid 2x2, warp tile 64x64 (ratio 4.0). 4-stage pipeline, Kc=32.
#define PITCH  80
#define BUFA   (128*PITCH)                 /* 10240 */
#define BUFB   (128*PITCH)                 /* 10240 */
#define OFF_B  BUFA
#define STGB   (BUFA+BUFB)                 /* 20480 */
#define NSTG   4
#define OFF_DEC (NSTG*STGB)                /* 81920: 128 floats */
#define OFF_WC  (OFF_DEC+512)
#define OFF_V   (OFF_WC+512)
#define OFF_COV (OFF_V+512)                /* 128 floats */
#define OFF_RED (OFF_COV+512)              /* 128*2 floats */
#define OFF_SC  (OFF_RED+1024)
#define SMEM_SZ (OFF_SC+512)               /* 85504 B */

__device__ __forceinline__ void load_stage(uint32_t sb, int s,
                                           int row0, int m0, int k0, int tid) {
    const uint32_t base = sb + s * STGB;
#pragma unroll
    for (int it = 0; it < 4; ++it) {   // A: 128 rows x 4 chunks
        const int idx = tid + it * 128;
        const int row = idx >> 2, ch = idx & 3;
        const uint32_t o = row * PITCH + ch * 16;
        const size_t g = (size_t)(row0 + row) * NDIM + k0 + ch * 8;
        cp16(base + o, g_h16 + g);
    }
#pragma unroll
    for (int it = 0; it < 4; ++it) {   // B: 128 rows x 4 chunks
        const int idx = tid + it * 128;
        const int row = idx >> 2, ch = idx & 3;
        const uint32_t o = row * PITCH + ch * 16;
        const size_t g = (size_t)(m0 + row) * NDIM + k0 + ch * 8;
        cp16(base + OFF_B + o, g_w + g);
    }
}

__global__ __launch_bounds__(128, 2)
void score_mma_kernel(const float* __restrict__ coverage,
                      const float* __restrict__ W_c,
                      const float* __restrict__ v) {
    extern __shared__ char smem[];
    const uint32_t sb = smem_to_u32(smem);
    const int tid  = threadIdx.x;
    const int lane = tid & 31;
    const int wid  = tid >> 5;
    const int wm   = wid >> 1;          // 0..1 (64-row slab)
    const int wn   = wid & 1;           // 0..1 (64-col slab)
    const int row0 = blockIdx.x * 128;
    const int b    = row0 / TT;

    float* dec_s = (float*)(smem + OFF_DEC);
    float* wc_s  = (float*)(smem + OFF_WC);
    float* v_s   = (float*)(smem + OFF_V);
    float* cov_s = (float*)(smem + OFF_COV);
    float* red   = (float*)(smem + OFF_RED);   // [128][2]
    float* sc_s  = (float*)(smem + OFF_SC);

    cov_s[tid] = coverage[row0 + tid];
    sc_s[tid]  = 0.f;

    const uint32_t aoff = (uint32_t)((wm*64 + (lane&7) + ((lane>>3)&1)*8) * PITCH + (lane>>4)*16);
    const uint32_t boff = (uint32_t)((wn*64 + (lane&7)) * PITCH + (lane>>3)*16);

    for (int nc = 0; nc < 8; ++nc) {
        const int m0 = nc * 128;
        dec_s[tid] = g_dec_fea[b * NDIM + m0 + tid];
        wc_s[tid]  = W_c[m0 + tid];
        v_s[tid]   = v[m0 + tid];

        float acc[4][8][4];
#pragma unroll
        for (int mi = 0; mi < 4; ++mi)
#pragma unroll
            for (int ni = 0; ni < 8; ++ni)
#pragma unroll
                for (int q = 0; q < 4; ++q) acc[mi][ni][q] = 0.f;

        load_stage(sb, 0, row0, m0, 0,  tid); CP_COMMIT();
        load_stage(sb, 1, row0, m0, 32, tid); CP_COMMIT();
        load_stage(sb, 2, row0, m0, 64, tid); CP_COMMIT();

        for (int ks = 0; ks < 32; ++ks) {
            const int s = ks & 3;
            if (ks + 3 < 32) CP_WAIT_2(); else CP_WAIT_0();
            __syncthreads();
            const uint32_t stg = sb + s * STGB;

            uint32_t bh[8][4];
#pragma unroll
            for (int ni = 0; ni < 8; ++ni)
                ldm_x4(bh[ni], stg + OFF_B + boff + ni * (8 * PITCH));
            uint32_t a0[4][4];
#pragma unroll
            for (int mi = 0; mi < 4; ++mi)
                ldm_x4(a0[mi], stg + aoff + mi * (16 * PITCH));

            if (ks + 3 < 32) {
                load_stage(sb, (ks + 3) & 3, row0, m0, (ks + 3) * 32, tid);
                CP_COMMIT();
            }

            // kk = 0
#pragma unroll
            for (int mi = 0; mi < 4; ++mi)
#pragma unroll
                for (int ni = 0; ni < 8; ++ni)
                    mma16816(acc[mi][ni], a0[mi], &bh[ni][0]);
            // kk = 1
            uint32_t a1[4][4];
#pragma unroll
            for (int mi = 0; mi < 4; ++mi)
                ldm_x4(a1[mi], stg + aoff + mi * (16 * PITCH) + 32);
#pragma unroll
            for (int mi = 0; mi < 4; ++mi)
#pragma unroll
                for (int ni = 0; ni < 8; ++ni)
                    mma16816(acc[mi][ni], a1[mi], &bh[ni][2]);
        }

        // fused epilogue: fast tanh + dot with v over this 128-col chunk
        float part[4][2];
#pragma unroll
        for (int mi = 0; mi < 4; ++mi) { part[mi][0] = 0.f; part[mi][1] = 0.f; }
#pragma unroll
        for (int mi = 0; mi < 4; ++mi) {
            const int r0 = wm*64 + mi*16 + (lane >> 2);
            const float cv0 = cov_s[r0], cv1 = cov_s[r0 + 8];
#pragma unroll
            for (int ni = 0; ni < 8; ++ni) {
                const int c0 = wn*64 + ni*8 + (lane & 3)*2;
                const float d0 = dec_s[c0],  d1 = dec_s[c0+1];
                const float w0 = wc_s[c0],   w1 = wc_s[c0+1];
                const float q0 = v_s[c0],    q1 = v_s[c0+1];
                part[mi][0] += fast_tanh(acc[mi][ni][0] + d0 + cv0*w0) * q0
                             + fast_tanh(acc[mi][ni][1] + d1 + cv0*w1) * q1;
                part[mi][1] += fast_tanh(acc[mi][ni][2] + d0 + cv1*w0) * q0
                             + fast_tanh(acc[mi][ni][3] + d1 + cv1*w1) * q1;
            }
        }
#pragma unroll
        for (int mi = 0; mi < 4; ++mi)
#pragma unroll
            for (int i = 0; i < 2; ++i) {
                float p = part[mi][i];
                p += __shfl_xor_sync(0xffffffffu, p, 1);
                p += __shfl_xor_sync(0xffffffffu, p, 2);
                if ((lane & 3) == 0)
                    red[(wm*64 + mi*16 + (lane >> 2) + 8*i) * 2 + wn] = p;
            }
        __syncthreads();
        sc_s[tid] += red[tid*2] + red[tid*2+1];
        __syncthreads();
    }

    g_scores[row0 + tid] = sc_s[tid];
}

// ---------------- softmax ----------------
__global__ void softmax_kernel(const float* __restrict__ mask,
                               const float* __restrict__ coverage,
                               float* __restrict__ attn_out,
                               float* __restrict__ cov_out) {
    const int b = blockIdx.x, tid = threadIdx.x;
    __shared__ float wr_[8], stat[2];
    const float* sc = g_scores + b * TT;
    float sv[4], lmax = -1e30f;
#pragma unroll
    for (int q = 0; q < 4; ++q) { sv[q] = sc[tid + 256 * q]; lmax = fmaxf(lmax, sv[q]); }
#pragma unroll
    for (int off = 16; off; off >>= 1) lmax = fmaxf(lmax, __shfl_xor_sync(0xffffffffu, lmax, off));
    if ((tid & 31) == 0) wr_[tid >> 5] = lmax;
    __syncthreads();
    if (tid == 0) {
        float m = wr_[0];
#pragma unroll
        for (int i = 1; i < 8; ++i) m = fmaxf(m, wr_[i]);
        stat[0] = m;
    }
    __syncthreads();
    const float M = stat[0];
    float e[4], lsum = 0.f;
#pragma unroll
    for (int q = 0; q < 4; ++q) { e[q] = expf(sv[q] - M) * mask[b * TT + tid + 256 * q]; lsum += e[q]; }
#pragma unroll
    for (int off = 16; off; off >>= 1) lsum += __shfl_xor_sync(0xffffffffu, lsum, off);
    if ((tid & 31) == 0) wr_[tid >> 5] = lsum;
    __syncthreads();
    if (tid == 0) {
        float s = 0.f;
#pragma unroll
        for (int i = 0; i < 8; ++i) s += wr_[i];
        stat[1] = 1.0f / s;
    }
    __syncthreads();
    const float inv = stat[1];
#pragma unroll
    for (int q = 0; q < 4; ++q) {
        const int t = tid + 256 * q;
        const float a = e[q] * inv;
        attn_out[b * TT + t] = a;
        cov_out[b * TT + t]  = coverage[b * TT + t] + a;
    }
}

// ---------------- c_t: 4-way T-split on fp16 h + reduce ----------------
__global__ void ct_part_kernel(const float* __restrict__ attn) {
    const int b = blockIdx.x, nb = blockIdx.y, tc = blockIdx.z;
    const int n2 = nb * 128 + threadIdx.x;           // half2 column index
    __shared__ float a_s[256];
    for (int i = threadIdx.x; i < 256; i += 128)
        a_s[i] = attn[b * TT + tc * 256 + i];
    __syncthreads();
    const __half2* hb = (const __half2*)g_h16 + (size_t)(b * TT + tc * 256) * (NDIM/2) + n2;
    float s0 = 0.f, s1 = 0.f;
#pragma unroll 4
    for (int t = 0; t < 256; ++t) {
        const float2 hv = __half22float2(hb[(size_t)t * (NDIM/2)]);
        const float a = a_s[t];
        s0 += a * hv.x;
        s1 += a * hv.y;
    }
    float2* outp = (float2*)(g_ct_part + ((size_t)tc * BB + b) * NDIM) + n2;
    *outp = make_float2(s0, s1);
}
__global__ void ct_reduce_kernel(float* __restrict__ c_t) {
    const int i = blockIdx.x * 256 + threadIdx.x;
    c_t[i] = (g_ct_part[i] + g_ct_part[i + BB * NDIM]) +
             (g_ct_part[i + 2 * BB * NDIM] + g_ct_part[i + 3 * BB * NDIM]);
}

// ---------------------------------------------------------------------------
extern "C" void kernel_launch(void* const* d_in, const int* in_sizes, int n_in,
                              void* d_out, int out_size) {
    const float* s_t_hat  = (const float*)d_in[0];
    const float* h        = (const float*)d_in[1];
    const float* mask     = (const float*)d_in[2];
    const float* coverage = (const float*)d_in[3];
    const float* W_h      = (const float*)d_in[4];
    const float* W_c      = (const float*)d_in[5];
    const float* dec_W    = (const float*)d_in[6];
    const float* dec_b    = (const float*)d_in[7];
    const float* v        = (const float*)d_in[8];

    float* out  = (float*)d_out;
    float* c_t  = out;
    float* attn = out + (size_t)BB * NDIM;
    float* covn = attn + (size_t)BB * TT;

    cudaFuncSetAttribute(score_mma_kernel,
                         cudaFuncAttributeMaxDynamicSharedMemorySize, SMEM_SZ);

    conv_kernel<<<H_BLOCKS + W_BLOCKS, 256>>>(h, W_h);
    dec_fea_kernel<<<NDIM / 8, 256>>>(s_t_hat, dec_W, dec_b);
    score_mma_kernel<<<MTOT / 128, 128, SMEM_SZ>>>(coverage, W_c, v);
    softmax_kernel<<<BB, 256>>>(mask, coverage, attn, covn);
    ct_part_kernel<<<dim3(BB, 4, 4), 128>>>(attn);
    ct_reduce_kernel<<<BB * NDIM / 256, 256>>>(c_t);
}

// round 15
// speedup vs baseline: 1.0709x; 1.0082x over previous
#include <cuda_runtime.h>
#include <cuda_fp16.h>
#include <math.h>
#include <stdint.h>

#define BB 64
#define TT 1024
#define NDIM 1024
#define MTOT (BB*TT)

__device__ __align__(16) __half g_h16[(size_t)MTOT*NDIM];
__device__ __align__(16) __half g_w[(size_t)NDIM*NDIM];
__device__ float g_dec_fea[BB*NDIM];
__device__ float g_scores[MTOT];
__device__ float g_ct_part[4*BB*NDIM];

#define H_BLOCKS ((int)((size_t)MTOT * NDIM / 4 / 256))   /* 65536 */
#define W_BLOCKS (NDIM * NDIM / 4 / 256)                  /* 1024 */

// ---------------- helpers ----------------
__device__ __forceinline__ uint32_t smem_to_u32(const void* p) {
    uint32_t a;
    asm("{ .reg .u64 t; cvta.to.shared.u64 t, %1; cvt.u32.u64 %0, t; }" : "=r"(a) : "l"(p));
    return a;
}
__device__ __forceinline__ void cp16(uint32_t dst, const void* src) {
    asm volatile("cp.async.cg.shared.global [%0], [%1], 16;" :: "r"(dst), "l"(src));
}
#define CP_COMMIT() asm volatile("cp.async.commit_group;" ::: "memory")
#define CP_WAIT_1() asm volatile("cp.async.wait_group 1;" ::: "memory")
#define CP_WAIT_0() asm volatile("cp.async.wait_group 0;" ::: "memory")

__device__ __forceinline__ void ldm_x4(uint32_t* r, uint32_t addr) {
    asm volatile("ldmatrix.sync.aligned.m8n8.x4.shared.b16 {%0,%1,%2,%3}, [%4];"
        : "=r"(r[0]), "=r"(r[1]), "=r"(r[2]), "=r"(r[3]) : "r"(addr));
}
__device__ __forceinline__ void mma16816(float* d, const uint32_t* a, const uint32_t* b) {
    asm volatile("mma.sync.aligned.m16n8k16.row.col.f32.f16.f16.f32 "
        "{%0,%1,%2,%3}, {%4,%5,%6,%7}, {%8,%9}, {%0,%1,%2,%3};"
        : "+f"(d[0]), "+f"(d[1]), "+f"(d[2]), "+f"(d[3])
        : "r"(a[0]), "r"(a[1]), "r"(a[2]), "r"(a[3]), "r"(b[0]), "r"(b[1]));
}
// fast tanh: 1 - 2/(e^{2x}+1); exact saturation at +-1; err ~1e-6
__device__ __forceinline__ float fast_tanh(float x) {
    const float e = __expf(2.0f * x);
    return 1.0f - __fdividef(2.0f, e + 1.0f);
}

// ---------------- convert f32 -> fp16 (h and W in one kernel) ----------------
__global__ void conv_kernel(const float* __restrict__ h, const float* __restrict__ w) {
    const int blk = blockIdx.x;
    if (blk < H_BLOCKS) {
        const size_t i = (size_t)blk * 256 + threadIdx.x;
        float4 x = ((const float4*)h)[i];
        __half2* H = (__half2*)g_h16;
        H[2*i]   = __halves2half2(__float2half_rn(x.x), __float2half_rn(x.y));
        H[2*i+1] = __halves2half2(__float2half_rn(x.z), __float2half_rn(x.w));
    } else {
        const size_t i = (size_t)(blk - H_BLOCKS) * 256 + threadIdx.x;
        float4 x = ((const float4*)w)[i];
        __half2* W = (__half2*)g_w;
        W[2*i]   = __halves2half2(__float2half_rn(x.x), __float2half_rn(x.y));
        W[2*i+1] = __halves2half2(__float2half_rn(x.z), __float2half_rn(x.w));
    }
}

// ---------------- dec_fea ----------------
__global__ void dec_fea_kernel(const float* __restrict__ s_t_hat,
                               const float* __restrict__ dec_W,
                               const float* __restrict__ dec_b) {
    const int warp = threadIdx.x >> 5, lane = threadIdx.x & 31;
    const int m = blockIdx.x * 8 + warp;
    const float* wr = dec_W + (size_t)m * NDIM + lane;
    float w[32];
#pragma unroll
    for (int j = 0; j < 32; ++j) w[j] = wr[j * 32];
    const float bias = dec_b[m];
    for (int b = 0; b < BB; ++b) {
        const float* s = s_t_hat + (size_t)b * NDIM + lane;
        float acc = 0.f;
#pragma unroll
        for (int j = 0; j < 32; ++j) acc += w[j] * s[j * 32];
#pragma unroll
        for (int off = 16; off; off >>= 1) acc += __shfl_down_sync(0xffffffffu, acc, off);
        if (lane == 0) g_dec_fea[b * NDIM + m] = acc + bias;
    }
}

// ---------------- score kernel: 128x128 CTA tile, Kc=64, NSTG=3, 2 CTAs/SM ----------------
#define PITCH  144                          /* 128B row + 16B skew pad */
#define BUFA   (128*PITCH)                  /* 18432 */
#define OFF_B  BUFA
#define STGB   (2*BUFA)                     /* 36864 */
#define NSTG   3
#define OFF_DEC (NSTG*STGB)                 /* 110592: 128 floats */
#define OFF_WC  (OFF_DEC+512)
#define OFF_V   (OFF_WC+512)
#define OFF_COV (OFF_V+512)                 /* 128 floats */
#define OFF_RED (OFF_COV+512)               /* 128*2 floats */
#define OFF_SC  (OFF_RED+1024)
#define SMEM_SZ (OFF_SC+512)                /* 114176 B */

__device__ __forceinline__ void load_stage(uint32_t sb, int s,
                                           int row0, int m0, int k0, int tid) {
    const uint32_t base = sb + s * STGB;
#pragma unroll
    for (int it = 0; it < 8; ++it) {   // A: 128 rows x 8 chunks of 16B
        const int idx = tid + it * 128;
        const int row = idx >> 3, ch = idx & 7;
        const uint32_t o = row * PITCH + ch * 16;
        cp16(base + o, g_h16 + (size_t)(row0 + row) * NDIM + k0 + ch * 8);
    }
#pragma unroll
    for (int it = 0; it < 8; ++it) {   // B: 128 rows x 8 chunks
        const int idx = tid + it * 128;
        const int row = idx >> 3, ch = idx & 7;
        const uint32_t o = row * PITCH + ch * 16;
        cp16(base + OFF_B + o, g_w + (size_t)(m0 + row) * NDIM + k0 + ch * 8);
    }
}

__global__ __launch_bounds__(128, 2)
void score_mma_kernel(const float* __restrict__ coverage,
                      const float* __restrict__ W_c,
                      const float* __restrict__ v) {
    extern __shared__ char smem[];
    const uint32_t sb = smem_to_u32(smem);
    const int tid  = threadIdx.x;
    const int lane = tid & 31;
    const int wid  = tid >> 5;
    const int wm   = wid >> 1;          // 0..1 (64-row slab)
    const int wn   = wid & 1;           // 0..1 (64-col slab)
    const int row0 = blockIdx.x * 128;
    const int b    = row0 / TT;

    float* dec_s = (float*)(smem + OFF_DEC);
    float* wc_s  = (float*)(smem + OFF_WC);
    float* v_s   = (float*)(smem + OFF_V);
    float* cov_s = (float*)(smem + OFF_COV);
    float* red   = (float*)(smem + OFF_RED);   // [128][2]
    float* sc_s  = (float*)(smem + OFF_SC);

    cov_s[tid] = coverage[row0 + tid];
    sc_s[tid]  = 0.f;

    const uint32_t aoff = (uint32_t)((wm*64 + (lane&7) + ((lane>>3)&1)*8) * PITCH + (lane>>4)*16);
    const uint32_t boff = (uint32_t)((wn*64 + (lane&7)) * PITCH + (lane>>3)*16);

    for (int nc = 0; nc < 8; ++nc) {
        const int m0 = nc * 128;
        dec_s[tid] = g_dec_fea[b * NDIM + m0 + tid];
        wc_s[tid]  = W_c[m0 + tid];
        v_s[tid]   = v[m0 + tid];

        float acc[4][8][4];
#pragma unroll
        for (int mi = 0; mi < 4; ++mi)
#pragma unroll
            for (int ni = 0; ni < 8; ++ni)
#pragma unroll
                for (int q = 0; q < 4; ++q) acc[mi][ni][q] = 0.f;

        load_stage(sb, 0, row0, m0, 0,  tid); CP_COMMIT();
        load_stage(sb, 1, row0, m0, 64, tid); CP_COMMIT();

        for (int ks = 0; ks < 16; ++ks) {
            const int s = ks % 3;
            if (ks + 2 < 16) CP_WAIT_1(); else CP_WAIT_0();
            __syncthreads();
            const uint32_t stg = sb + s * STGB;

            // first half: k0..31
            uint32_t bh[8][4];
#pragma unroll
            for (int ni = 0; ni < 8; ++ni)
                ldm_x4(bh[ni], stg + OFF_B + boff + ni * (8 * PITCH));
            uint32_t a0[4][4];
#pragma unroll
            for (int mi = 0; mi < 4; ++mi)
                ldm_x4(a0[mi], stg + aoff + mi * (16 * PITCH));

            if (ks + 2 < 16) {
                load_stage(sb, (ks + 2) % 3, row0, m0, (ks + 2) * 64, tid);
                CP_COMMIT();
            }

#pragma unroll
            for (int mi = 0; mi < 4; ++mi)
#pragma unroll
                for (int ni = 0; ni < 8; ++ni)
                    mma16816(acc[mi][ni], a0[mi], &bh[ni][0]);
            uint32_t a1[4][4];
#pragma unroll
            for (int mi = 0; mi < 4; ++mi)
                ldm_x4(a1[mi], stg + aoff + mi * (16 * PITCH) + 32);
#pragma unroll
            for (int mi = 0; mi < 4; ++mi)
#pragma unroll
                for (int ni = 0; ni < 8; ++ni)
                    mma16816(acc[mi][ni], a1[mi], &bh[ni][2]);

            // second half: k32..63
#pragma unroll
            for (int ni = 0; ni < 8; ++ni)
                ldm_x4(bh[ni], stg + OFF_B + boff + ni * (8 * PITCH) + 64);
            uint32_t a2[4][4];
#pragma unroll
            for (int mi = 0; mi < 4; ++mi)
                ldm_x4(a2[mi], stg + aoff + mi * (16 * PITCH) + 64);
#pragma unroll
            for (int mi = 0; mi < 4; ++mi)
#pragma unroll
                for (int ni = 0; ni < 8; ++ni)
                    mma16816(acc[mi][ni], a2[mi], &bh[ni][0]);
            uint32_t a3[4][4];
#pragma unroll
            for (int mi = 0; mi < 4; ++mi)
                ldm_x4(a3[mi], stg + aoff + mi * (16 * PITCH) + 96);
#pragma unroll
            for (int mi = 0; mi < 4; ++mi)
#pragma unroll
                for (int ni = 0; ni < 8; ++ni)
                    mma16816(acc[mi][ni], a3[mi], &bh[ni][2]);
        }

        // fused epilogue: fast tanh + dot with v over this 128-col chunk
        float part[4][2];
#pragma unroll
        for (int mi = 0; mi < 4; ++mi) { part[mi][0] = 0.f; part[mi][1] = 0.f; }
#pragma unroll
        for (int mi = 0; mi < 4; ++mi) {
            const int r0 = wm*64 + mi*16 + (lane >> 2);
            const float cv0 = cov_s[r0], cv1 = cov_s[r0 + 8];
#pragma unroll
            for (int ni = 0; ni < 8; ++ni) {
                const int c0 = wn*64 + ni*8 + (lane & 3)*2;
                const float d0 = dec_s[c0],  d1 = dec_s[c0+1];
                const float w0 = wc_s[c0],   w1 = wc_s[c0+1];
                const float q0 = v_s[c0],    q1 = v_s[c0+1];
                part[mi][0] += fast_tanh(acc[mi][ni][0] + d0 + cv0*w0) * q0
                             + fast_tanh(acc[mi][ni][1] + d1 + cv0*w1) * q1;
                part[mi][1] += fast_tanh(acc[mi][ni][2] + d0 + cv1*w0) * q0
                             + fast_tanh(acc[mi][ni][3] + d1 + cv1*w1) * q1;
            }
        }
#pragma unroll
        for (int mi = 0; mi < 4; ++mi)
#pragma unroll
            for (int i = 0; i < 2; ++i) {
                float p = part[mi][i];
                p += __shfl_xor_sync(0xffffffffu, p, 1);
                p += __shfl_xor_sync(0xffffffffu, p, 2);
                if ((lane & 3) == 0)
                    red[(wm*64 + mi*16 + (lane >> 2) + 8*i) * 2 + wn] = p;
            }
        __syncthreads();
        sc_s[tid] += red[tid*2] + red[tid*2+1];
        __syncthreads();
    }

    g_scores[row0 + tid] = sc_s[tid];
}

// ---------------- softmax ----------------
__global__ void softmax_kernel(const float* __restrict__ mask,
                               const float* __restrict__ coverage,
                               float* __restrict__ attn_out,
                               float* __restrict__ cov_out) {
    const int b = blockIdx.x, tid = threadIdx.x;
    __shared__ float wr_[8], stat[2];
    const float* sc = g_scores + b * TT;
    float sv[4], lmax = -1e30f;
#pragma unroll
    for (int q = 0; q < 4; ++q) { sv[q] = sc[tid + 256 * q]; lmax = fmaxf(lmax, sv[q]); }
#pragma unroll
    for (int off = 16; off; off >>= 1) lmax = fmaxf(lmax, __shfl_xor_sync(0xffffffffu, lmax, off));
    if ((tid & 31) == 0) wr_[tid >> 5] = lmax;
    __syncthreads();
    if (tid == 0) {
        float m = wr_[0];
#pragma unroll
        for (int i = 1; i < 8; ++i) m = fmaxf(m, wr_[i]);
        stat[0] = m;
    }
    __syncthreads();
    const float M = stat[0];
    float e[4], lsum = 0.f;
#pragma unroll
    for (int q = 0; q < 4; ++q) { e[q] = expf(sv[q] - M) * mask[b * TT + tid + 256 * q]; lsum += e[q]; }
#pragma unroll
    for (int off = 16; off; off >>= 1) lsum += __shfl_xor_sync(0xffffffffu, lsum, off);
    if ((tid & 31) == 0) wr_[tid >> 5] = lsum;
    __syncthreads();
    if (tid == 0) {
        float s = 0.f;
#pragma unroll
        for (int i = 0; i < 8; ++i) s += wr_[i];
        stat[1] = 1.0f / s;
    }
    __syncthreads();
    const float inv = stat[1];
#pragma unroll
    for (int q = 0; q < 4; ++q) {
        const int t = tid + 256 * q;
        const float a = e[q] * inv;
        attn_out[b * TT + t] = a;
        cov_out[b * TT + t]  = coverage[b * TT + t] + a;
    }
}

// ---------------- c_t: 4-way T-split on fp16 h + reduce ----------------
__global__ void ct_part_kernel(const float* __restrict__ attn) {
    const int b = blockIdx.x, nb = blockIdx.y, tc = blockIdx.z;
    const int n2 = nb * 128 + threadIdx.x;           // half2 column index
    __shared__ float a_s[256];
    for (int i = threadIdx.x; i < 256; i += 128)
        a_s[i] = attn[b * TT + tc * 256 + i];
    __syncthreads();
    const __half2* hb = (const __half2*)g_h16 + (size_t)(b * TT + tc * 256) * (NDIM/2) + n2;
    float s0 = 0.f, s1 = 0.f;
#pragma unroll 4
    for (int t = 0; t < 256; ++t) {
        const float2 hv = __half22float2(hb[(size_t)t * (NDIM/2)]);
        const float a = a_s[t];
        s0 += a * hv.x;
        s1 += a * hv.y;
    }
    float2* outp = (float2*)(g_ct_part + ((size_t)tc * BB + b) * NDIM) + n2;
    *outp = make_float2(s0, s1);
}
__global__ void ct_reduce_kernel(float* __restrict__ c_t) {
    const int i = blockIdx.x * 256 + threadIdx.x;
    c_t[i] = (g_ct_part[i] + g_ct_part[i + BB * NDIM]) +
             (g_ct_part[i + 2 * BB * NDIM] + g_ct_part[i + 3 * BB * NDIM]);
}

// ---------------------------------------------------------------------------
extern "C" void kernel_launch(void* const* d_in, const int* in_sizes, int n_in,
                              void* d_out, int out_size) {
    const float* s_t_hat  = (const float*)d_in[0];
    const float* h        = (const float*)d_in[1];
    const float* mask     = (const float*)d_in[2];
    const float* coverage = (const float*)d_in[3];
    const float* W_h      = (const float*)d_in[4];
    const float* W_c      = (const float*)d_in[5];
    const float* dec_W    = (const float*)d_in[6];
    const float* dec_b    = (const float*)d_in[7];
    const float* v        = (const float*)d_in[8];

    float* out  = (float*)d_out;
    float* c_t  = out;
    float* attn = out + (size_t)BB * NDIM;
    float* covn = attn + (size_t)BB * TT;

    cudaFuncSetAttribute(score_mma_kernel,
                         cudaFuncAttributeMaxDynamicSharedMemorySize, SMEM_SZ);

    conv_kernel<<<H_BLOCKS + W_BLOCKS, 256>>>(h, W_h);
    dec_fea_kernel<<<NDIM / 8, 256>>>(s_t_hat, dec_W, dec_b);
    score_mma_kernel<<<MTOT / 128, 128, SMEM_SZ>>>(coverage, W_c, v);
    softmax_kernel<<<BB, 256>>>(mask, coverage, attn, covn);
    ct_part_kernel<<<dim3(BB, 4, 4), 128>>>(attn);
    ct_reduce_kernel<<<BB * NDIM / 256, 256>>>(c_t);
}

// round 17
// speedup vs baseline: 1.3837x; 1.2922x over previous
#include <cuda_runtime.h>
#include <cuda_fp16.h>
#include <math.h>
#include <stdint.h>

#define BB 64
#define TT 1024
#define NDIM 1024
#define MTOT (BB*TT)

__device__ __align__(16) __half g_h16[(size_t)MTOT*NDIM];
__device__ __align__(16) __half g_w[(size_t)NDIM*NDIM];
__device__ float g_dec_fea[BB*NDIM];
__device__ float g_scores[MTOT];
__device__ float g_ct_part[4*BB*NDIM];

#define H_PAIRS ((size_t)MTOT * NDIM / 8)   /* 8388608: 8-float groups in h */
#define W_PAIRS ((size_t)NDIM * NDIM / 8)   /* 131072 */

// ---------------- helpers ----------------
__device__ __forceinline__ uint32_t smem_to_u32(const void* p) {
    uint32_t a;
    asm("{ .reg .u64 t; cvta.to.shared.u64 t, %1; cvt.u32.u64 %0, t; }" : "=r"(a) : "l"(p));
    return a;
}
__device__ __forceinline__ void cp16(uint32_t dst, const void* src) {
    asm volatile("cp.async.cg.shared.global [%0], [%1], 16;" :: "r"(dst), "l"(src));
}
#define CP_COMMIT() asm volatile("cp.async.commit_group;" ::: "memory")
#define CP_WAIT_1() asm volatile("cp.async.wait_group 1;" ::: "memory")
#define CP_WAIT_0() asm volatile("cp.async.wait_group 0;" ::: "memory")

__device__ __forceinline__ void ldm_x4(uint32_t* r, uint32_t addr) {
    asm volatile("ldmatrix.sync.aligned.m8n8.x4.shared.b16 {%0,%1,%2,%3}, [%4];"
        : "=r"(r[0]), "=r"(r[1]), "=r"(r[2]), "=r"(r[3]) : "r"(addr));
}
__device__ __forceinline__ void mma16816(float* d, const uint32_t* a, const uint32_t* b) {
    asm volatile("mma.sync.aligned.m16n8k16.row.col.f32.f16.f16.f32 "
        "{%0,%1,%2,%3}, {%4,%5,%6,%7}, {%8,%9}, {%0,%1,%2,%3};"
        : "+f"(d[0]), "+f"(d[1]), "+f"(d[2]), "+f"(d[3])
        : "r"(a[0]), "r"(a[1]), "r"(a[2]), "r"(a[3]), "r"(b[0]), "r"(b[1]));
}
// fast tanh: 1 - 2/(e^{2x}+1); exact saturation at +-1; err ~1e-6
__device__ __forceinline__ float fast_tanh(float x) {
    const float e = __expf(2.0f * x);
    return 1.0f - __fdividef(2.0f, e + 1.0f);
}
__device__ __forceinline__ uint32_t pack_h2(float a, float b) {
    __half2 hv = __floats2half2_rn(a, b);
    uint32_t u;
    memcpy(&u, &hv, 4);
    return u;
}

// ---------------- convert f32 -> fp16 (grid-stride, 16B stores) ----------------
__global__ void conv_kernel(const float* __restrict__ h, const float* __restrict__ w) {
    const size_t stride = (size_t)gridDim.x * blockDim.x;
    const size_t t0 = (size_t)blockIdx.x * blockDim.x + threadIdx.x;
    const float4* h4 = (const float4*)h;
    uint4* H = (uint4*)g_h16;
    for (size_t i = t0; i < H_PAIRS; i += stride) {
        float4 x0 = h4[2*i], x1 = h4[2*i+1];
        uint4 u;
        u.x = pack_h2(x0.x, x0.y); u.y = pack_h2(x0.z, x0.w);
        u.z = pack_h2(x1.x, x1.y); u.w = pack_h2(x1.z, x1.w);
        H[i] = u;
    }
    const float4* w4 = (const float4*)w;
    uint4* W = (uint4*)g_w;
    for (size_t i = t0; i < W_PAIRS; i += stride) {
        float4 x0 = w4[2*i], x1 = w4[2*i+1];
        uint4 u;
        u.x = pack_h2(x0.x, x0.y); u.y = pack_h2(x0.z, x0.w);
        u.z = pack_h2(x1.x, x1.y); u.w = pack_h2(x1.z, x1.w);
        W[i] = u;
    }
}

// ---------------- dec_fea: grid (128 m-groups, 8 b-groups) ----------------
__global__ void dec_fea_kernel(const float* __restrict__ s_t_hat,
                               const float* __restrict__ dec_W,
                               const float* __restrict__ dec_b) {
    const int warp = threadIdx.x >> 5, lane = threadIdx.x & 31;
    const int m = blockIdx.x * 8 + warp;
    const int b0 = blockIdx.y * 8;
    const float* wr = dec_W + (size_t)m * NDIM + lane;
    float w[32];
#pragma unroll
    for (int j = 0; j < 32; ++j) w[j] = wr[j * 32];
    const float bias = dec_b[m];
#pragma unroll
    for (int bq = 0; bq < 8; ++bq) {
        const int b = b0 + bq;
        const float* s = s_t_hat + (size_t)b * NDIM + lane;
        float acc = 0.f;
#pragma unroll
        for (int j = 0; j < 32; ++j) acc += w[j] * s[j * 32];
#pragma unroll
        for (int off = 16; off; off >>= 1) acc += __shfl_down_sync(0xffffffffu, acc, off);
        if (lane == 0) g_dec_fea[b * NDIM + m] = acc + bias;
    }
}

// ---------------- score kernel: 128x128 CTA tile, Kc=64, NSTG=3, 2 CTAs/SM ----------------
#define PITCH  144                          /* 128B row + 16B skew pad */
#define BUFA   (128*PITCH)                  /* 18432 */
#define OFF_B  BUFA
#define STGB   (2*BUFA)                     /* 36864 */
#define NSTG   3
#define OFF_DEC (NSTG*STGB)                 /* 110592: 128 floats */
#define OFF_WC  (OFF_DEC+512)
#define OFF_V   (OFF_WC+512)
#define OFF_COV (OFF_V+512)                 /* 128 floats */
#define OFF_RED (OFF_COV+512)               /* 128*2 floats */
#define OFF_SC  (OFF_RED+1024)
#define SMEM_SZ (OFF_SC+512)                /* 114176 B */

__device__ __forceinline__ void load_stage(uint32_t sb, int s,
                                           int row0, int m0, int k0, int tid) {
    const uint32_t base = sb + s * STGB;
#pragma unroll
    for (int it = 0; it < 8; ++it) {   // A: 128 rows x 8 chunks of 16B
        const int idx = tid + it * 128;
        const int row = idx >> 3, ch = idx & 7;
        const uint32_t o = row * PITCH + ch * 16;
        cp16(base + o, g_h16 + (size_t)(row0 + row) * NDIM + k0 + ch * 8);
    }
#pragma unroll
    for (int it = 0; it < 8; ++it) {   // B: 128 rows x 8 chunks
        const int idx = tid + it * 128;
        const int row = idx >> 3, ch = idx & 7;
        const uint32_t o = row * PITCH + ch * 16;
        cp16(base + OFF_B + o, g_w + (size_t)(m0 + row) * NDIM + k0 + ch * 8);
    }
}

__global__ __launch_bounds__(128, 2)
void score_mma_kernel(const float* __restrict__ coverage,
                      const float* __restrict__ W_c,
                      const float* __restrict__ v) {
    extern __shared__ char smem[];
    const uint32_t sb = smem_to_u32(smem);
    const int tid  = threadIdx.x;
    const int lane = tid & 31;
    const int wid  = tid >> 5;
    const int wm   = wid >> 1;          // 0..1 (64-row slab)
    const int wn   = wid & 1;           // 0..1 (64-col slab)
    const int row0 = blockIdx.x * 128;
    const int b    = row0 / TT;

    float* dec_s = (float*)(smem + OFF_DEC);
    float* wc_s  = (float*)(smem + OFF_WC);
    float* v_s   = (float*)(smem + OFF_V);
    float* cov_s = (float*)(smem + OFF_COV);
    float* red   = (float*)(smem + OFF_RED);   // [128][2]
    float* sc_s  = (float*)(smem + OFF_SC);

    cov_s[tid] = coverage[row0 + tid];
    sc_s[tid]  = 0.f;

    const uint32_t aoff = (uint32_t)((wm*64 + (lane&7) + ((lane>>3)&1)*8) * PITCH + (lane>>4)*16);
    const uint32_t boff = (uint32_t)((wn*64 + (lane&7)) * PITCH + (lane>>3)*16);

    for (int nc = 0; nc < 8; ++nc) {
        const int m0 = nc * 128;
        dec_s[tid] = g_dec_fea[b * NDIM + m0 + tid];
        wc_s[tid]  = W_c[m0 + tid];
        v_s[tid]   = v[m0 + tid];

        float acc[4][8][4];
#pragma unroll
        for (int mi = 0; mi < 4; ++mi)
#pragma unroll
            for (int ni = 0; ni < 8; ++ni)
#pragma unroll
                for (int q = 0; q < 4; ++q) acc[mi][ni][q] = 0.f;

        load_stage(sb, 0, row0, m0, 0,  tid); CP_COMMIT();
        load_stage(sb, 1, row0, m0, 64, tid); CP_COMMIT();

        for (int ks = 0; ks < 16; ++ks) {
            const int s = ks % 3;
            if (ks + 2 < 16) CP_WAIT_1(); else CP_WAIT_0();
            __syncthreads();
            const uint32_t stg = sb + s * STGB;

            // first half: k0..31
            uint32_t bh[8][4];
#pragma unroll
            for (int ni = 0; ni < 8; ++ni)
                ldm_x4(bh[ni], stg + OFF_B + boff + ni * (8 * PITCH));
            uint32_t a0[4][4];
#pragma unroll
            for (int mi = 0; mi < 4; ++mi)
                ldm_x4(a0[mi], stg + aoff + mi * (16 * PITCH));

            if (ks + 2 < 16) {
                load_stage(sb, (ks + 2) % 3, row0, m0, (ks + 2) * 64, tid);
                CP_COMMIT();
            }

#pragma unroll
            for (int mi = 0; mi < 4; ++mi)
#pragma unroll
                for (int ni = 0; ni < 8; ++ni)
                    mma16816(acc[mi][ni], a0[mi], &bh[ni][0]);
            uint32_t a1[4][4];
#pragma unroll
            for (int mi = 0; mi < 4; ++mi)
                ldm_x4(a1[mi], stg + aoff + mi * (16 * PITCH) + 32);
#pragma unroll
            for (int mi = 0; mi < 4; ++mi)
#pragma unroll
                for (int ni = 0; ni < 8; ++ni)
                    mma16816(acc[mi][ni], a1[mi], &bh[ni][2]);

            // second half: k32..63
#pragma unroll
            for (int ni = 0; ni < 8; ++ni)
                ldm_x4(bh[ni], stg + OFF_B + boff + ni * (8 * PITCH) + 64);
            uint32_t a2[4][4];
#pragma unroll
            for (int mi = 0; mi < 4; ++mi)
                ldm_x4(a2[mi], stg + aoff + mi * (16 * PITCH) + 64);
#pragma unroll
            for (int mi = 0; mi < 4; ++mi)
#pragma unroll
                for (int ni = 0; ni < 8; ++ni)
                    mma16816(acc[mi][ni], a2[mi], &bh[ni][0]);
            uint32_t a3[4][4];
#pragma unroll
            for (int mi = 0; mi < 4; ++mi)
                ldm_x4(a3[mi], stg + aoff + mi * (16 * PITCH) + 96);
#pragma unroll
            for (int mi = 0; mi < 4; ++mi)
#pragma unroll
                for (int ni = 0; ni < 8; ++ni)
                    mma16816(acc[mi][ni], a3[mi], &bh[ni][2]);
        }

        // fused epilogue: fast tanh + dot with v over this 128-col chunk
        float part[4][2];
#pragma unroll
        for (int mi = 0; mi < 4; ++mi) { part[mi][0] = 0.f; part[mi][1] = 0.f; }
#pragma unroll
        for (int mi = 0; mi < 4; ++mi) {
            const int r0 = wm*64 + mi*16 + (lane >> 2);
            const float cv0 = cov_s[r0], cv1 = cov_s[r0 + 8];
#pragma unroll
            for (int ni = 0; ni < 8; ++ni) {
                const int c0 = wn*64 + ni*8 + (lane & 3)*2;
                const float d0 = dec_s[c0],  d1 = dec_s[c0+1];
                const float w0 = wc_s[c0],   w1 = wc_s[c0+1];
                const float q0 = v_s[c0],    q1 = v_s[c0+1];
                part[mi][0] += fast_tanh(acc[mi][ni][0] + d0 + cv0*w0) * q0
                             + fast_tanh(acc[mi][ni][1] + d1 + cv0*w1) * q1;
                part[mi][1] += fast_tanh(acc[mi][ni][2] + d0 + cv1*w0) * q0
                             + fast_tanh(acc[mi][ni][3] + d1 + cv1*w1) * q1;
            }
        }
#pragma unroll
        for (int mi = 0; mi < 4; ++mi)
#pragma unroll
            for (int i = 0; i < 2; ++i) {
                float p = part[mi][i];
                p += __shfl_xor_sync(0xffffffffu, p, 1);
                p += __shfl_xor_sync(0xffffffffu, p, 2);
                if ((lane & 3) == 0)
                    red[(wm*64 + mi*16 + (lane >> 2) + 8*i) * 2 + wn] = p;
            }
        __syncthreads();
        sc_s[tid] += red[tid*2] + red[tid*2+1];
        __syncthreads();
    }

    g_scores[row0 + tid] = sc_s[tid];
}

// ---------------- softmax ----------------
__global__ void softmax_kernel(const float* __restrict__ mask,
                               const float* __restrict__ coverage,
                               float* __restrict__ attn_out,
                               float* __restrict__ cov_out) {
    const int b = blockIdx.x, tid = threadIdx.x;
    __shared__ float wr_[8], stat[2];
    const float* sc = g_scores + b * TT;
    float sv[4], lmax = -1e30f;
#pragma unroll
    for (int q = 0; q < 4; ++q) { sv[q] = sc[tid + 256 * q]; lmax = fmaxf(lmax, sv[q]); }
#pragma unroll
    for (int off = 16; off; off >>= 1) lmax = fmaxf(lmax, __shfl_xor_sync(0xffffffffu, lmax, off));
    if ((tid & 31) == 0) wr_[tid >> 5] = lmax;
    __syncthreads();
    if (tid == 0) {
        float m = wr_[0];
#pragma unroll
        for (int i = 1; i < 8; ++i) m = fmaxf(m, wr_[i]);
        stat[0] = m;
    }
    __syncthreads();
    const float M = stat[0];
    float e[4], lsum = 0.f;
#pragma unroll
    for (int q = 0; q < 4; ++q) { e[q] = expf(sv[q] - M) * mask[b * TT + tid + 256 * q]; lsum += e[q]; }
#pragma unroll
    for (int off = 16; off; off >>= 1) lsum += __shfl_xor_sync(0xffffffffu, lsum, off);
    if ((tid & 31) == 0) wr_[tid >> 5] = lsum;
    __syncthreads();
    if (tid == 0) {
        float s = 0.f;
#pragma unroll
        for (int i = 0; i < 8; ++i) s += wr_[i];
        stat[1] = 1.0f / s;
    }
    __syncthreads();
    const float inv = stat[1];
#pragma unroll
    for (int q = 0; q < 4; ++q) {
        const int t = tid + 256 * q;
        const float a = e[q] * inv;
        attn_out[b * TT + t] = a;
        cov_out[b * TT + t]  = coverage[b * TT + t] + a;
    }
}

// ---------------- c_t: 4-way T-split on fp16 h + reduce ----------------
__global__ void ct_part_kernel(const float* __restrict__ attn) {
    const int b = blockIdx.x, nb = blockIdx.y, tc = blockIdx.z;
    const int n2 = nb * 128 + threadIdx.x;           // half2 column index
    __shared__ float a_s[256];
    for (int i = threadIdx.x; i < 256; i += 128)
        a_s[i] = attn[b * TT + tc * 256 + i];
    __syncthreads();
    const __half2* hb = (const __half2*)g_h16 + (size_t)(b * TT + tc * 256) * (NDIM/2) + n2;
    float s0 = 0.f, s1 = 0.f;
    for (int t = 0; t < 256; t += 8) {
        __half2 hv[8];
#pragma unroll
        for (int u = 0; u < 8; ++u) hv[u] = hb[(size_t)(t + u) * (NDIM/2)];
#pragma unroll
        for (int u = 0; u < 8; ++u) {
            const float2 f = __half22float2(hv[u]);
            const float a = a_s[t + u];
            s0 += a * f.x;
            s1 += a * f.y;
        }
    }
    float2* outp = (float2*)(g_ct_part + ((size_t)tc * BB + b) * NDIM) + n2;
    *outp = make_float2(s0, s1);
}
__global__ void ct_reduce_kernel(float* __restrict__ c_t) {
    const int i = blockIdx.x * 256 + threadIdx.x;
    c_t[i] = (g_ct_part[i] + g_ct_part[i + BB * NDIM]) +
             (g_ct_part[i + 2 * BB * NDIM] + g_ct_part[i + 3 * BB * NDIM]);
}

// ---------------------------------------------------------------------------
extern "C" void kernel_launch(void* const* d_in, const int* in_sizes, int n_in,
                              void* d_out, int out_size) {
    const float* s_t_hat  = (const float*)d_in[0];
    const float* h        = (const float*)d_in[1];
    const float* mask     = (const float*)d_in[2];
    const float* coverage = (const float*)d_in[3];
    const float* W_h      = (const float*)d_in[4];
    const float* W_c      = (const float*)d_in[5];
    const float* dec_W    = (const float*)d_in[6];
    const float* dec_b    = (const float*)d_in[7];
    const float* v        = (const float*)d_in[8];

    float* out  = (float*)d_out;
    float* c_t  = out;
    float* attn = out + (size_t)BB * NDIM;
    float* covn = attn + (size_t)BB * TT;

    cudaFuncSetAttribute(score_mma_kernel,
                         cudaFuncAttributeMaxDynamicSharedMemorySize, SMEM_SZ);

    conv_kernel<<<1184, 256>>>(h, W_h);
    dec_fea_kernel<<<dim3(NDIM / 8, 8), 256>>>(s_t_hat, dec_W, dec_b);
    score_mma_kernel<<<MTOT / 128, 128, SMEM_SZ>>>(coverage, W_c, v);
    softmax_kernel<<<BB, 256>>>(mask, coverage, attn, covn);
    ct_part_kernel<<<dim3(BB, 4, 4), 128>>>(attn);
    ct_reduce_kernel<<<BB * NDIM / 256, 256>>>(c_t);
}